// round 10
// baseline (speedup 1.0000x reference)
#include <cuda_runtime.h>
#include <cstdint>

#define BB   32
#define TT   1024
#define HID  512
#define G4   2048            // 4*HID
#define MROWS (BB*TT)        // 32768
#define NCTA 128
#define OUT_MAIN (BB*TT*HID) // 16777216

typedef unsigned long long ull;

__device__ __forceinline__ ull pack2(float x) {
    ull d; asm("mov.b64 %0, {%1, %1};" : "=l"(d) : "f"(x)); return d;
}
__device__ __forceinline__ ull fma2(ull a, ull b, ull c) {
    ull d; asm("fma.rn.f32x2 %0, %1, %2, %3;" : "=l"(d) : "l"(a), "l"(b), "l"(c)); return d;
}
__device__ __forceinline__ ull add2(ull a, ull b) {
    ull d; asm("add.rn.f32x2 %0, %1, %2;" : "=l"(d) : "l"(a), "l"(b)); return d;
}
__device__ __forceinline__ void unpack2(ull v, float& lo, float& hi) {
    asm("mov.b64 {%0, %1}, %2;" : "=f"(lo), "=f"(hi) : "l"(v));
}

// -------------------- device scratch --------------------
__device__ float g_G[(size_t)MROWS * G4];           // precomputed input-side gates
__device__ float g_Y0[(size_t)(TT + 1) * BB * HID]; // layer-0 h outputs (slot t+1 = h_t)
__device__ unsigned g_flag2[2][8][NCTA];            // [layer][warp-group][cta] epoch flags

// -------------------- big GEMM (FFMA2); block(0,0) zeroes this layer's flags ----
template <int MODE>
__global__ __launch_bounds__(256) void gemm_kernel(
    const float* __restrict__ A,
    const float* __restrict__ W,
    const float* __restrict__ bih,
    const float* __restrict__ bhh,
    float* __restrict__ Gout)
{
    __shared__ float As[16 * 132];
    __shared__ float Bs[16 * 66];

    const int tid = threadIdx.x;
    const int bm = blockIdx.y;
    const int bn = blockIdx.x;
    const int ty = tid >> 4;
    const int tx = tid & 15;

    if (bm == 0 && bn == 0) {
        unsigned* ff = &g_flag2[MODE][0][0];
        for (int i = tid; i < 8 * NCTA; i += 256) ff[i] = 0u;
    }

    ull acc2[8][2];
#pragma unroll
    for (int i = 0; i < 8; i++) { acc2[i][0] = 0ULL; acc2[i][1] = 0ULL; }

    for (int kt = 0; kt < HID; kt += 16) {
#pragma unroll
        for (int q = 0; q < 2; q++) {
            int idx = tid + q * 256;
            int lrow = idx >> 2;
            int lk = (idx & 3) << 2;
            int r = bm * 128 + lrow;
            const float* ap;
            if (MODE == 0)
                ap = A + ((size_t)(r & 31) * TT + (size_t)(r >> 5)) * HID;
            else
                ap = A + (size_t)r * HID;
            float4 v = *(const float4*)(ap + kt + lk);
            As[(lk + 0) * 132 + lrow] = v.x;
            As[(lk + 1) * 132 + lrow] = v.y;
            As[(lk + 2) * 132 + lrow] = v.z;
            As[(lk + 3) * 132 + lrow] = v.w;
        }
        {
            int ln = tid >> 2;
            int lk = (tid & 3) << 2;
            float4 v = *(const float4*)(W + (size_t)(bn * 64 + ln) * HID + kt + lk);
            Bs[(lk + 0) * 66 + ln] = v.x;
            Bs[(lk + 1) * 66 + ln] = v.y;
            Bs[(lk + 2) * 66 + ln] = v.z;
            Bs[(lk + 3) * 66 + ln] = v.w;
        }
        __syncthreads();

#pragma unroll
        for (int k = 0; k < 16; k++) {
            float4 a0 = *(const float4*)&As[k * 132 + 4 * ty];
            float4 a1 = *(const float4*)&As[k * 132 + 64 + 4 * ty];
            ull bp0 = *(const ull*)&Bs[k * 66 + 2 * tx];
            ull bp1 = *(const ull*)&Bs[k * 66 + 32 + 2 * tx];
            float av[8] = {a0.x, a0.y, a0.z, a0.w, a1.x, a1.y, a1.z, a1.w};
#pragma unroll
            for (int i = 0; i < 8; i++) {
                ull ad = pack2(av[i]);
                acc2[i][0] = fma2(ad, bp0, acc2[i][0]);
                acc2[i][1] = fma2(ad, bp1, acc2[i][1]);
            }
        }
        __syncthreads();
    }

    int c0 = bn * 64 + 2 * tx;
    int c1 = c0 + 32;
    float bias00 = bih[c0] + bhh[c0];
    float bias01 = bih[c0 + 1] + bhh[c0 + 1];
    float bias10 = bih[c1] + bhh[c1];
    float bias11 = bih[c1 + 1] + bhh[c1 + 1];
#pragma unroll
    for (int i = 0; i < 8; i++) {
        int m = (i < 4) ? (4 * ty + i) : (64 + 4 * ty + i - 4);
        size_t r = (size_t)(bm * 128 + m);
        float x, y;
        unpack2(acc2[i][0], x, y);
        *(float2*)(Gout + r * G4 + c0) = make_float2(x + bias00, y + bias01);
        unpack2(acc2[i][1], x, y);
        *(float2*)(Gout + r * G4 + c1) = make_float2(x + bias10, y + bias11);
    }
}

// -------------------- persistent recurrence kernel: warp-autonomous ----------
// CTA = 4 hidden units (j0..j0+3) = 16 gate rows. Warp wb owns batches
// 4wb..4wb+3 and computes their COMPLETE gates (no k-split). Lane (b_loc, gh):
// accumulates gates gh and gh+8 over all k via (k,k+1)-paired FFMA2.
// No __syncthreads in the step loop; sync is per-(warp-group, cta) flags.
//
// smem: ws  float[16][516]  @ 0      (33024 B)  -- 16 gate weight rows
//       h   float[8][4][516]@ 33024  (66048 B)  -- per-warp 4 staged h rows
#define SMR_WS   0
#define SMR_H    33024
#define SMR_TOT  99072

__global__ __launch_bounds__(256, 1) void recur_kernel(
    int layer,
    const float* __restrict__ Whh,
    const float* __restrict__ h0l,
    const float* __restrict__ c0l,
    float* __restrict__ out)
{
    extern __shared__ char smraw[];
    float* ws    = (float*)(smraw + SMR_WS);
    float* hbase = (float*)(smraw + SMR_H);

    const int tid = threadIdx.x;
    const int cta = blockIdx.x;
    const int j0 = cta * 4;

    // ---- build weight rows ws[g][k], g = tt*4 + u (16 rows, stride 516) ----
    {
        int g = tid >> 4;                     // 0..15
        int l = tid & 15;
        const float* src = Whh + (size_t)((g >> 2) * HID + j0 + (g & 3)) * HID;
        float* dst = ws + g * 516;
#pragma unroll
        for (int kk = 0; kk < 32; kk++) {
            int k = l + kk * 16;
            dst[k] = src[k];
        }
    }
    __syncthreads();   // once; none inside the step loop

    const int wb    = tid >> 5;               // warp-group = batch group
    const int lane  = tid & 31;
    const int b_loc = lane >> 3;              // 0..3
    const int gh    = lane & 7;               // gate-half: gates gh and gh+8
    const int u     = gh;                     // activation lane if u<4
    const int batch = wb * 4 + b_loc;
    const bool act  = (u < 4);

    float* h_w = hbase + wb * (4 * 516) + b_loc * 516;   // this lane's h row
    const float* w1 = ws + gh * 516;                     // gate gh
    const float* w2 = ws + (gh + 8) * 516;               // gate gh+8

    const int gcol1 = (gh >> 2) * HID + j0 + (gh & 3);        // i/f gates
    const int gcol2 = ((gh + 8) >> 2) * HID + j0 + (gh & 3);  // g/o gates

    float creg = 0.f;
    if (act) creg = c0l[(size_t)batch * HID + j0 + u];

    unsigned* myflag = &g_flag2[layer][wb][cta];
    const unsigned* pollp = &g_flag2[layer][wb][lane * 4];

    float* outh = out + OUT_MAIN;
    float* outc = out + OUT_MAIN + 2 * BB * HID;

    for (int t = 0; t < TT; t++) {
        // ---- input-side gates (independent of producers; issue early) ----
        const float* gro = g_G + (size_t)(t * BB + batch) * G4;
        float Gv1 = gro[gcol1];
        float Gv2 = gro[gcol2];

        // ---- wait for this warp-group's 128 producers (4 flags per lane) ----
        if (t > 0) {
            int spins = 0;
            while (true) {
                unsigned v0, v1, v2, v3;
                asm volatile("ld.acquire.gpu.global.u32 %0, [%1];" : "=r"(v0) : "l"(pollp)     : "memory");
                asm volatile("ld.acquire.gpu.global.u32 %0, [%1];" : "=r"(v1) : "l"(pollp + 1) : "memory");
                asm volatile("ld.acquire.gpu.global.u32 %0, [%1];" : "=r"(v2) : "l"(pollp + 2) : "memory");
                asm volatile("ld.acquire.gpu.global.u32 %0, [%1];" : "=r"(v3) : "l"(pollp + 3) : "memory");
                unsigned tt_ = (unsigned)t;
                bool ok = (v0 >= tt_) && (v1 >= tt_) && (v2 >= tt_) && (v3 >= tt_);
                if (__all_sync(0xffffffffu, ok)) break;
                if (++spins > 32) __nanosleep(40);
            }
        }

        // ---- stage this lane's h row slice (k-interleaved, conflict-free) ----
        const float* srow;
        if (layer == 0)
            srow = (t == 0) ? (h0l + (size_t)batch * HID)
                            : (g_Y0 + ((size_t)t * BB + batch) * HID);
        else
            srow = (t == 0) ? (h0l + (size_t)batch * HID)
                            : (out + ((size_t)batch * TT + (t - 1)) * HID);
#pragma unroll
        for (int i = 0; i < 16; i++) {
            int kq = gh + 8 * i;              // quarter-warp covers 128B chunks
            float4 v = __ldcv((const float4*)srow + kq);
            *(float4*)(h_w + 4 * kq) = v;
        }
        __syncwarp();

        // ---- mainloop: (k,k+1)-paired FFMA2, 2 gates per lane ----
        ull a1a = 0ULL, a1b = 0ULL, a2a = 0ULL, a2b = 0ULL;
#pragma unroll 4
        for (int k = 0; k < HID; k += 8) {
            ulonglong2 ha = *(const ulonglong2*)(h_w + k);       // pairs k01,k23
            ulonglong2 hb = *(const ulonglong2*)(h_w + k + 4);   // pairs k45,k67
            ulonglong2 wa = *(const ulonglong2*)(w1 + k);
            ulonglong2 wbv = *(const ulonglong2*)(w1 + k + 4);
            ulonglong2 wc = *(const ulonglong2*)(w2 + k);
            ulonglong2 wd = *(const ulonglong2*)(w2 + k + 4);
            a1a = fma2(ha.x, wa.x, a1a);
            a1b = fma2(ha.y, wa.y, a1b);
            a2a = fma2(ha.x, wc.x, a2a);
            a2b = fma2(ha.y, wc.y, a2b);
            a1a = fma2(hb.x, wbv.x, a1a);
            a1b = fma2(hb.y, wbv.y, a1b);
            a2a = fma2(hb.x, wd.x, a2a);
            a2b = fma2(hb.y, wd.y, a2b);
        }
        float lo, hi, x1, x2;
        unpack2(add2(a1a, a1b), lo, hi);  x1 = (lo + hi) + Gv1;   // gate gh
        unpack2(add2(a2a, a2b), lo, hi);  x2 = (lo + hi) + Gv2;   // gate gh+8

        // ---- gather i,f,g,o per (batch, u): xi/xg local, xf/xo from lane (b,4+u) ----
        int srcl = (lane & 24) + 4 + u;           // harmless for u>=4 (unused)
        float xf = __shfl_sync(0xffffffffu, x1, srcl);
        float xo = __shfl_sync(0xffffffffu, x2, srcl);

        float hval = 0.f;
        if (act) {
            float iv = 1.f / (1.f + __expf(-x1));
            float fv = 1.f / (1.f + __expf(-xf));
            float gv = 1.f - 2.f / (__expf(2.f * x2) + 1.f);
            float ov = 1.f / (1.f + __expf(-xo));
            float c = fv * creg + iv * gv;
            creg = c;
            hval = ov * (1.f - 2.f / (__expf(2.f * c) + 1.f));
        }

        // ---- publish h: gather 4 unit values to lane (b,0), one STG.128/batch ----
        float h0v = __shfl_sync(0xffffffffu, hval, (lane & 24) + 0);
        float h1v = __shfl_sync(0xffffffffu, hval, (lane & 24) + 1);
        float h2v = __shfl_sync(0xffffffffu, hval, (lane & 24) + 2);
        float h3v = __shfl_sync(0xffffffffu, hval, (lane & 24) + 3);
        if (gh == 0) {
            float4 hv4 = make_float4(h0v, h1v, h2v, h3v);
            float* dsth = (layer == 0)
                ? (g_Y0 + ((size_t)(t + 1) * BB + batch) * HID + j0)
                : (out + ((size_t)batch * TT + t) * HID + j0);
            __stcg((float4*)dsth, hv4);
        }
        if (t == TT - 1 && act) {
            outh[(size_t)(layer * BB + batch) * HID + j0 + u] = hval;
            outc[(size_t)(layer * BB + batch) * HID + j0 + u] = creg;
        }
        __syncwarp();
        if (lane == 0) {
            asm volatile("membar.gl;" ::: "memory");
            asm volatile("st.relaxed.gpu.global.u32 [%0], %1;"
                         :: "l"(myflag), "r"((unsigned)(t + 1)) : "memory");
        }
        // no __syncthreads: warps run autonomously
    }
}

// -------------------- launch --------------------
extern "C" void kernel_launch(void* const* d_in, const int* in_sizes, int n_in,
                              void* d_out, int out_size) {
    const float* input = (const float*)d_in[0];
    const float* h0    = (const float*)d_in[1];
    const float* c0    = (const float*)d_in[2];
    const float* W_ih  = (const float*)d_in[3];
    const float* W_hh  = (const float*)d_in[4];
    const float* b_ih  = (const float*)d_in[5];
    const float* b_hh  = (const float*)d_in[6];
    float* out = (float*)d_out;

    cudaFuncSetAttribute(recur_kernel, cudaFuncAttributeMaxDynamicSharedMemorySize, SMR_TOT);

    float* Gptr;
    cudaGetSymbolAddress((void**)&Gptr, g_G);
    float* Y0ptr;
    cudaGetSymbolAddress((void**)&Y0ptr, g_Y0);

    dim3 ggrid(32, 256);

    // Layer 0 (gemm<0> zeroes layer-0 flags, stream-ordered before recur)
    gemm_kernel<0><<<ggrid, 256>>>(input, W_ih, b_ih, b_hh, Gptr);
    recur_kernel<<<NCTA, 256, SMR_TOT>>>(0, W_hh, h0, c0, out);

    // Layer 1 (gemm<1> zeroes layer-1 flags; input = layer-0 outputs)
    gemm_kernel<1><<<ggrid, 256>>>(Y0ptr + BB * HID, W_ih + (size_t)G4 * HID,
                                   b_ih + G4, b_hh + G4, Gptr);
    recur_kernel<<<NCTA, 256, SMR_TOT>>>(1, W_hh + (size_t)G4 * HID,
                                         h0 + BB * HID, c0 + BB * HID, out);
}

// round 13
// speedup vs baseline: 1.7614x; 1.7614x over previous
#include <cuda_runtime.h>
#include <cstdint>

#define BB   32
#define TT   1024
#define HID  512
#define G4   2048            // 4*HID
#define MROWS (BB*TT)        // 32768
#define NCTA 128
#define OUT_MAIN (BB*TT*HID) // 16777216

typedef unsigned long long ull;

__device__ __forceinline__ ull pack2(float x) {
    ull d; asm("mov.b64 %0, {%1, %1};" : "=l"(d) : "f"(x)); return d;
}
__device__ __forceinline__ ull fma2(ull a, ull b, ull c) {
    ull d; asm("fma.rn.f32x2 %0, %1, %2, %3;" : "=l"(d) : "l"(a), "l"(b), "l"(c)); return d;
}
__device__ __forceinline__ ull add2(ull a, ull b) {
    ull d; asm("add.rn.f32x2 %0, %1, %2;" : "=l"(d) : "l"(a), "l"(b)); return d;
}
__device__ __forceinline__ void unpack2(ull v, float& lo, float& hi) {
    asm("mov.b64 {%0, %1}, %2;" : "=f"(lo), "=f"(hi) : "l"(v));
}

// -------------------- device scratch --------------------
__device__ float g_G[(size_t)MROWS * G4];           // precomputed input-side gates
__device__ float g_Y0[(size_t)(TT + 1) * BB * HID]; // layer-0 h outputs (slot t+1 = h_t)
__device__ unsigned g_gf[2][NCTA * 32];             // per-CTA epoch flags, 128B padded

// -------------------- big GEMM (FFMA2); block(0,0) zeroes this layer's flags ----
template <int MODE>
__global__ __launch_bounds__(256) void gemm_kernel(
    const float* __restrict__ A,
    const float* __restrict__ W,
    const float* __restrict__ bih,
    const float* __restrict__ bhh,
    float* __restrict__ Gout)
{
    __shared__ float As[16 * 132];
    __shared__ float Bs[16 * 66];

    const int tid = threadIdx.x;
    const int bm = blockIdx.y;
    const int bn = blockIdx.x;
    const int ty = tid >> 4;
    const int tx = tid & 15;

    if (bm == 0 && bn == 0) {
        unsigned* ff = &g_gf[MODE][0];
#pragma unroll
        for (int i = 0; i < 16; i++) ff[tid + i * 256] = 0u;
    }

    ull acc2[8][2];
#pragma unroll
    for (int i = 0; i < 8; i++) { acc2[i][0] = 0ULL; acc2[i][1] = 0ULL; }

    for (int kt = 0; kt < HID; kt += 16) {
#pragma unroll
        for (int q = 0; q < 2; q++) {
            int idx = tid + q * 256;
            int lrow = idx >> 2;
            int lk = (idx & 3) << 2;
            int r = bm * 128 + lrow;
            const float* ap;
            if (MODE == 0)
                ap = A + ((size_t)(r & 31) * TT + (size_t)(r >> 5)) * HID;
            else
                ap = A + (size_t)r * HID;
            float4 v = *(const float4*)(ap + kt + lk);
            As[(lk + 0) * 132 + lrow] = v.x;
            As[(lk + 1) * 132 + lrow] = v.y;
            As[(lk + 2) * 132 + lrow] = v.z;
            As[(lk + 3) * 132 + lrow] = v.w;
        }
        {
            int ln = tid >> 2;
            int lk = (tid & 3) << 2;
            float4 v = *(const float4*)(W + (size_t)(bn * 64 + ln) * HID + kt + lk);
            Bs[(lk + 0) * 66 + ln] = v.x;
            Bs[(lk + 1) * 66 + ln] = v.y;
            Bs[(lk + 2) * 66 + ln] = v.z;
            Bs[(lk + 3) * 66 + ln] = v.w;
        }
        __syncthreads();

#pragma unroll
        for (int k = 0; k < 16; k++) {
            float4 a0 = *(const float4*)&As[k * 132 + 4 * ty];
            float4 a1 = *(const float4*)&As[k * 132 + 64 + 4 * ty];
            ull bp0 = *(const ull*)&Bs[k * 66 + 2 * tx];
            ull bp1 = *(const ull*)&Bs[k * 66 + 32 + 2 * tx];
            float av[8] = {a0.x, a0.y, a0.z, a0.w, a1.x, a1.y, a1.z, a1.w};
#pragma unroll
            for (int i = 0; i < 8; i++) {
                ull ad = pack2(av[i]);
                acc2[i][0] = fma2(ad, bp0, acc2[i][0]);
                acc2[i][1] = fma2(ad, bp1, acc2[i][1]);
            }
        }
        __syncthreads();
    }

    int c0 = bn * 64 + 2 * tx;
    int c1 = c0 + 32;
    float bias00 = bih[c0] + bhh[c0];
    float bias01 = bih[c0 + 1] + bhh[c0 + 1];
    float bias10 = bih[c1] + bhh[c1];
    float bias11 = bih[c1 + 1] + bhh[c1 + 1];
#pragma unroll
    for (int i = 0; i < 8; i++) {
        int m = (i < 4) ? (4 * ty + i) : (64 + 4 * ty + i - 4);
        size_t r = (size_t)(bm * 128 + m);
        float x, y;
        unpack2(acc2[i][0], x, y);
        *(float2*)(Gout + r * G4 + c0) = make_float2(x + bias00, y + bias01);
        unpack2(acc2[i][1], x, y);
        *(float2*)(Gout + r * G4 + c1) = make_float2(x + bias10, y + bias11);
    }
}

// -------------------- persistent recurrence: 4 independent batch groups ----------
// Group g (of 4) = CTAs 32g..32g+31, owns batches 8g..8g+7 (ALL 512 units).
// CTA cl (in group) owns units j0=16*cl (64 gate rows). Thread (r=tid>>2, bp=tid&3)
// computes gate row r for batches 2bp, 2bp+1 over FULL k=512 (no k-split/reduce).
// Sync: per-CTA epoch flags, polled only by the 32 CTAs of the SAME group.
//
// Smem (bytes):
//   ws   : float[64][516]  @ 0       (132096)
//   h_s  : float[8][516]   @ 132096  (16512)
//   gates: float[512]      @ 148608  (2048)
//   hseg : float[160]      @ 150656  (640)
#define SM_WS    0
#define SM_HS    132096
#define SM_GT    148608
#define SM_HSEG  150656
#define SM_TOTAL 151296

__global__ __launch_bounds__(256, 1) void recur_kernel(
    int layer,
    const float* __restrict__ Whh,
    const float* __restrict__ h0l,
    const float* __restrict__ c0l,
    float* __restrict__ out)
{
    extern __shared__ char smraw[];
    float* ws      = (float*)(smraw + SM_WS);
    float* h_s     = (float*)(smraw + SM_HS);
    float* gates_s = (float*)(smraw + SM_GT);
    float* hseg    = (float*)(smraw + SM_HSEG);

    const int tid = threadIdx.x;
    const int cta = blockIdx.x;
    const int grp = cta >> 5;                 // group 0..3
    const int cl  = cta & 31;                 // CTA within group
    const int j0  = cl * 16;                  // unit base
    const int bbase = grp * 8;                // batch base

    // ---- load Whh slice: 64 rows (r = type*16+u), each thread a quarter-row ----
    {
        int r = tid >> 2, part = tid & 3;
        const float* src = Whh + ((size_t)((r >> 4) * HID + j0 + (r & 15))) * HID + part * 128;
        float* dst = ws + r * 516 + part * 128;
#pragma unroll
        for (int i = 0; i < 32; i++)
            *(float4*)(dst + i * 4) = *(const float4*)(src + i * 4);
    }

    // ---- act threads (tid<128): c state in regs; mapping u=tid>>3, b=tid&7 ----
    float creg = 0.f;
    const int au = tid >> 3, ab = tid & 7;
    if (tid < 128)
        creg = c0l[(size_t)(bbase + ab) * HID + j0 + au];
    __syncthreads();

    const int r  = tid >> 2;                  // gate row 0..63
    const int bp = tid & 3;                   // batch pair
    const int b0 = 2 * bp;
    const float* wrow  = ws + r * 516;
    const float* hrow0 = h_s + b0 * 516;
    const float* hrow1 = h_s + (b0 + 1) * 516;
    const int gcol = (r >> 4) * HID + j0 + (r & 15);   // G column for this row

    unsigned* myflag = &g_gf[layer][cta * 32];
    const unsigned* pollf = &g_gf[layer][(grp * 32 + tid) * 32];  // tid<32 only

    float* outh = out + OUT_MAIN;
    float* outc = out + OUT_MAIN + 2 * BB * HID;

    for (int t = 0; t < TT; t++) {
        // ---- input-side gate prefetch (independent of producers) ----
        size_t grow = ((size_t)t * BB + bbase + b0) * G4 + gcol;
        float Gv0 = g_G[grow];
        float Gv1 = g_G[grow + G4];

        // ---- wait for the 32 producers of THIS group (32 distinct lines) ----
        if (t > 0 && tid < 32) {
            unsigned v; int sp = 0;
            while (true) {
                asm volatile("ld.acquire.gpu.global.u32 %0, [%1];"
                             : "=r"(v) : "l"(pollf) : "memory");
                bool ok = (v >= (unsigned)t);
                if (__all_sync(0xffffffffu, ok)) break;
                if (++sp > 32) __nanosleep(20);
            }
        }
        __syncthreads();

        // ---- stage h (8 batches x 512) : L1-bypass loads (coherence!) ----
        if (layer == 0) {
            const float* src = (t == 0) ? (h0l + (size_t)bbase * HID)
                                        : (g_Y0 + ((size_t)t * BB + bbase) * HID);
#pragma unroll
            for (int i = 0; i < 4; i++) {
                int idx = tid + i * 256;              // 0..1023 float4s
                int row = idx >> 7, off = (idx & 127) << 2;
                float4 v = __ldcv((const float4*)(src + (size_t)row * HID + off));
                *(float4*)(h_s + row * 516 + off) = v;
            }
        } else {
#pragma unroll
            for (int i = 0; i < 4; i++) {
                int idx = tid + i * 256;
                int row = idx >> 7, off = (idx & 127) << 2;
                const float* src = (t == 0)
                    ? (h0l + (size_t)(bbase + row) * HID)
                    : (out + ((size_t)(bbase + row) * TT + (t - 1)) * HID);
                float4 v = __ldcv((const float4*)(src + off));
                *(float4*)(h_s + row * 516 + off) = v;
            }
        }
        __syncthreads();

        // ---- mainloop: full-k dot for (row r) x (batches b0,b0+1) ----
        ull a0a = 0ULL, a0b = 0ULL, a1a = 0ULL, a1b = 0ULL;
#pragma unroll 8
        for (int k = 0; k < HID; k += 8) {
            ulonglong2 w01 = *(const ulonglong2*)(wrow + k);
            ulonglong2 w23 = *(const ulonglong2*)(wrow + k + 4);
            ulonglong2 h00 = *(const ulonglong2*)(hrow0 + k);
            ulonglong2 h01 = *(const ulonglong2*)(hrow0 + k + 4);
            ulonglong2 h10 = *(const ulonglong2*)(hrow1 + k);
            ulonglong2 h11 = *(const ulonglong2*)(hrow1 + k + 4);
            a0a = fma2(h00.x, w01.x, a0a);
            a0b = fma2(h00.y, w01.y, a0b);
            a0a = fma2(h01.x, w23.x, a0a);
            a0b = fma2(h01.y, w23.y, a0b);
            a1a = fma2(h10.x, w01.x, a1a);
            a1b = fma2(h10.y, w01.y, a1b);
            a1a = fma2(h11.x, w23.x, a1a);
            a1b = fma2(h11.y, w23.y, a1b);
        }
        float lo, hi;
        unpack2(add2(a0a, a0b), lo, hi);
        float x0 = (lo + hi) + Gv0;
        unpack2(add2(a1a, a1b), lo, hi);
        float x1 = (lo + hi) + Gv1;

        // ---- exchange gates: gates_s[r*8 + b] (STS.64, conflict-free) ----
        *(float2*)(gates_s + r * 8 + b0) = make_float2(x0, x1);
        __syncthreads();

        // ---- activations: thread a<128 -> (u=a>>3, b=a&7); idx = a + type*128 ----
        if (tid < 128) {
            float xi = gates_s[tid];
            float xf = gates_s[128 + tid];
            float xg = gates_s[256 + tid];
            float xo = gates_s[384 + tid];
            float iv = 1.f / (1.f + __expf(-xi));
            float fv = 1.f / (1.f + __expf(-xf));
            float gv = 1.f - 2.f / (__expf(2.f * xg) + 1.f);
            float ov = 1.f / (1.f + __expf(-xo));
            float c = fv * creg + iv * gv;
            creg = c;
            float h = ov * (1.f - 2.f / (__expf(2.f * c) + 1.f));
            hseg[ab * 20 + au] = h;
            if (t == TT - 1) {
                outh[(size_t)(layer * BB + bbase + ab) * HID + j0 + au] = h;
                outc[(size_t)(layer * BB + bbase + ab) * HID + j0 + au] = creg;
            }
        }
        __syncthreads();

        // ---- publish 2KB (8 batches x 16 units) + release flag ----
        if (tid < 32) {
            int b = tid >> 2, q = tid & 3;
            float4 hv = *(const float4*)(hseg + b * 20 + 4 * q);
            float* dst = (layer == 0)
                ? (g_Y0 + ((size_t)(t + 1) * BB + bbase + b) * HID + j0 + 4 * q)
                : (out + ((size_t)(bbase + b) * TT + t) * HID + j0 + 4 * q);
            __stcg((float4*)dst, hv);
            __syncwarp();
            if (tid == 0) {
                __threadfence();
                asm volatile("st.relaxed.gpu.global.u32 [%0], %1;"
                             :: "l"(myflag), "r"((unsigned)(t + 1)) : "memory");
            }
        }
        __syncthreads();
    }
}

// -------------------- launch --------------------
extern "C" void kernel_launch(void* const* d_in, const int* in_sizes, int n_in,
                              void* d_out, int out_size) {
    const float* input = (const float*)d_in[0];
    const float* h0    = (const float*)d_in[1];
    const float* c0    = (const float*)d_in[2];
    const float* W_ih  = (const float*)d_in[3];
    const float* W_hh  = (const float*)d_in[4];
    const float* b_ih  = (const float*)d_in[5];
    const float* b_hh  = (const float*)d_in[6];
    float* out = (float*)d_out;

    cudaFuncSetAttribute(recur_kernel, cudaFuncAttributeMaxDynamicSharedMemorySize, SM_TOTAL);

    float* Gptr;
    cudaGetSymbolAddress((void**)&Gptr, g_G);
    float* Y0ptr;
    cudaGetSymbolAddress((void**)&Y0ptr, g_Y0);

    dim3 ggrid(32, 256);

    // Layer 0 (gemm<0> zeroes layer-0 flags, stream-ordered before recur)
    gemm_kernel<0><<<ggrid, 256>>>(input, W_ih, b_ih, b_hh, Gptr);
    recur_kernel<<<NCTA, 256, SM_TOTAL>>>(0, W_hh, h0, c0, out);

    // Layer 1 (gemm<1> zeroes layer-1 flags; input = layer-0 outputs)
    gemm_kernel<1><<<ggrid, 256>>>(Y0ptr + BB * HID, W_ih + (size_t)G4 * HID,
                                   b_ih + G4, b_hh + G4, Gptr);
    recur_kernel<<<NCTA, 256, SM_TOTAL>>>(1, W_hh + (size_t)G4 * HID,
                                          h0 + BB * HID, c0 + BB * HID, out);
}

// round 14
// speedup vs baseline: 2.8857x; 1.6383x over previous
#include <cuda_runtime.h>
#include <cstdint>

#define BB   32
#define TT   1024
#define HID  512
#define G4   2048            // 4*HID
#define MROWS (BB*TT)        // 32768
#define NCTA 128
#define OUT_MAIN (BB*TT*HID) // 16777216

typedef unsigned long long ull;

__device__ __forceinline__ ull pack2(float x) {
    ull d; asm("mov.b64 %0, {%1, %1};" : "=l"(d) : "f"(x)); return d;
}
__device__ __forceinline__ ull fma2(ull a, ull b, ull c) {
    ull d; asm("fma.rn.f32x2 %0, %1, %2, %3;" : "=l"(d) : "l"(a), "l"(b), "l"(c)); return d;
}
__device__ __forceinline__ void unpack2(ull v, float& lo, float& hi) {
    asm("mov.b64 {%0, %1}, %2;" : "=f"(lo), "=f"(hi) : "l"(v));
}

// -------------------- device scratch --------------------
__device__ float g_G[(size_t)MROWS * G4];           // precomputed input-side gates
__device__ float g_Y0[(size_t)(TT + 1) * BB * HID]; // layer-0 h outputs (slot t+1 = h_t)
__device__ unsigned g_gf[2][NCTA * 32];             // per-CTA epoch flags, 128B padded

// -------------------- big GEMM (FFMA2); block(0,0) zeroes this layer's flags ----
template <int MODE>
__global__ __launch_bounds__(256) void gemm_kernel(
    const float* __restrict__ A,
    const float* __restrict__ W,
    const float* __restrict__ bih,
    const float* __restrict__ bhh,
    float* __restrict__ Gout)
{
    __shared__ float As[16 * 132];
    __shared__ float Bs[16 * 66];

    const int tid = threadIdx.x;
    const int bm = blockIdx.y;
    const int bn = blockIdx.x;
    const int ty = tid >> 4;
    const int tx = tid & 15;

    if (bm == 0 && bn == 0) {
        unsigned* ff = &g_gf[MODE][0];
#pragma unroll
        for (int i = 0; i < 16; i++) ff[tid + i * 256] = 0u;
    }

    ull acc2[8][2];
#pragma unroll
    for (int i = 0; i < 8; i++) { acc2[i][0] = 0ULL; acc2[i][1] = 0ULL; }

    for (int kt = 0; kt < HID; kt += 16) {
#pragma unroll
        for (int q = 0; q < 2; q++) {
            int idx = tid + q * 256;
            int lrow = idx >> 2;
            int lk = (idx & 3) << 2;
            int r = bm * 128 + lrow;
            const float* ap;
            if (MODE == 0)
                ap = A + ((size_t)(r & 31) * TT + (size_t)(r >> 5)) * HID;
            else
                ap = A + (size_t)r * HID;
            float4 v = *(const float4*)(ap + kt + lk);
            As[(lk + 0) * 132 + lrow] = v.x;
            As[(lk + 1) * 132 + lrow] = v.y;
            As[(lk + 2) * 132 + lrow] = v.z;
            As[(lk + 3) * 132 + lrow] = v.w;
        }
        {
            int ln = tid >> 2;
            int lk = (tid & 3) << 2;
            float4 v = *(const float4*)(W + (size_t)(bn * 64 + ln) * HID + kt + lk);
            Bs[(lk + 0) * 66 + ln] = v.x;
            Bs[(lk + 1) * 66 + ln] = v.y;
            Bs[(lk + 2) * 66 + ln] = v.z;
            Bs[(lk + 3) * 66 + ln] = v.w;
        }
        __syncthreads();

#pragma unroll
        for (int k = 0; k < 16; k++) {
            float4 a0 = *(const float4*)&As[k * 132 + 4 * ty];
            float4 a1 = *(const float4*)&As[k * 132 + 64 + 4 * ty];
            ull bp0 = *(const ull*)&Bs[k * 66 + 2 * tx];
            ull bp1 = *(const ull*)&Bs[k * 66 + 32 + 2 * tx];
            float av[8] = {a0.x, a0.y, a0.z, a0.w, a1.x, a1.y, a1.z, a1.w};
#pragma unroll
            for (int i = 0; i < 8; i++) {
                ull ad = pack2(av[i]);
                acc2[i][0] = fma2(ad, bp0, acc2[i][0]);
                acc2[i][1] = fma2(ad, bp1, acc2[i][1]);
            }
        }
        __syncthreads();
    }

    int c0 = bn * 64 + 2 * tx;
    int c1 = c0 + 32;
    float bias00 = bih[c0] + bhh[c0];
    float bias01 = bih[c0 + 1] + bhh[c0 + 1];
    float bias10 = bih[c1] + bhh[c1];
    float bias11 = bih[c1 + 1] + bhh[c1 + 1];
#pragma unroll
    for (int i = 0; i < 8; i++) {
        int m = (i < 4) ? (4 * ty + i) : (64 + 4 * ty + i - 4);
        size_t r = (size_t)(bm * 128 + m);
        float x, y;
        unpack2(acc2[i][0], x, y);
        *(float2*)(Gout + r * G4 + c0) = make_float2(x + bias00, y + bias01);
        unpack2(acc2[i][1], x, y);
        *(float2*)(Gout + r * G4 + c1) = make_float2(x + bias10, y + bias11);
    }
}

// -------------------- persistent recurrence: batch groups + k-sliced warps -------
// Group g = CTAs 32g..32g+31, batches 8g..8g+7. CTA cl: units j0=16cl (64 rows).
// Warp w: k-slice [64w,64w+64) -> needs ONLY producers 4w..4w+3 of its group.
// Lane (rg=lane&15, bg=lane>>4): 4x4 tile rows {rg+16i} x batches {4bg+j}, f32x2
// over k-pairs. k-split 8 partials -> conflict-free scatter (stride 9) -> reduce.
//
// Smem (bytes):
//   ws   : float[64][516]  @ 0       (132096)
//   h_s  : float[8][516]   @ 132096  (16512)   (warp-private k slices)
//   red  : float[512*9]    @ 148608  (18432)
//   gates: float[512]      @ 167040  (2048)
//   hseg : float[160]      @ 169088  (640)
#define SM_WS    0
#define SM_HS    132096
#define SM_RED   148608
#define SM_GT    167040
#define SM_HSEG  169088
#define SM_TOTAL 169728

__global__ __launch_bounds__(256, 1) void recur_kernel(
    int layer,
    const float* __restrict__ Whh,
    const float* __restrict__ h0l,
    const float* __restrict__ c0l,
    float* __restrict__ out)
{
    extern __shared__ char smraw[];
    float* ws      = (float*)(smraw + SM_WS);
    float* h_s     = (float*)(smraw + SM_HS);
    float* red     = (float*)(smraw + SM_RED);
    float* gates_s = (float*)(smraw + SM_GT);
    float* hseg    = (float*)(smraw + SM_HSEG);

    const int tid = threadIdx.x;
    const int cta = blockIdx.x;
    const int grp = cta >> 5;
    const int cl  = cta & 31;
    const int j0  = cl * 16;
    const int bbase = grp * 8;

    // ---- load Whh slice: 64 rows (r = type*16+u), quarter-row per thread ----
    {
        int r = tid >> 2, part = tid & 3;
        const float* src = Whh + ((size_t)((r >> 4) * HID + j0 + (r & 15))) * HID + part * 128;
        float* dst = ws + r * 516 + part * 128;
#pragma unroll
        for (int i = 0; i < 32; i++)
            *(float4*)(dst + i * 4) = *(const float4*)(src + i * 4);
    }

    // ---- act threads (tid<128): c in regs; u=tid>>3, b=tid&7 ----
    float creg = 0.f;
    const int au = tid >> 3, ab = tid & 7;
    if (tid < 128)
        creg = c0l[(size_t)(bbase + ab) * HID + j0 + au];
    __syncthreads();

    const int widx = tid >> 5;
    const int lane = tid & 31;
    const int rg = lane & 15;
    const int bg = lane >> 4;
    const int kbase = widx * 64;

    // reduce-phase cells: c0=tid, c1=tid+256
    int rc0, bc0, rc1, bc1;
    {
        int c = tid;
        rc0 = (c & 15) + 16 * ((c >> 5) & 3);
        bc0 = 4 * ((c >> 4) & 1) + (c >> 7);
        c = tid + 256;
        rc1 = (c & 15) + 16 * ((c >> 5) & 3);
        bc1 = 4 * ((c >> 4) & 1) + (c >> 7);
    }
    const int gcol0 = (rc0 >> 4) * HID + j0 + (rc0 & 15);
    const int gcol1 = (rc1 >> 4) * HID + j0 + (rc1 & 15);

    unsigned* myflag = &g_gf[layer][cta * 32];
    const unsigned* pollf = &g_gf[layer][(grp * 32 + 4 * widx + (lane & 3)) * 32];

    float* outh = out + OUT_MAIN;
    float* outc = out + OUT_MAIN + 2 * BB * HID;

    for (int t = 0; t < TT; t++) {
        // ---- prefetch input-side gates for this thread's 2 reduce cells ----
        float Gv0 = g_G[((size_t)t * BB + bbase + bc0) * G4 + gcol0];
        float Gv1 = g_G[((size_t)t * BB + bbase + bc1) * G4 + gcol1];

        // ---- per-warp wait: only 4 producers (lanes 0..3 poll) ----
        if (t > 0) {
            int sp = 0;
            while (true) {
                bool ok = true;
                if (lane < 4) {
                    unsigned v;
                    asm volatile("ld.acquire.gpu.global.u32 %0, [%1];"
                                 : "=r"(v) : "l"(pollf) : "memory");
                    ok = (v >= (unsigned)t);
                }
                if (__all_sync(0xffffffffu, ok)) break;
                if (++sp > 512) __nanosleep(20);
            }
        }

        // ---- per-warp stage: 8 batches x 64 k (this warp's slice), L1-bypass ----
#pragma unroll
        for (int q = 0; q < 4; q++) {
            int idx = lane + 32 * q;          // 0..127
            int row = idx >> 4;               // batch row 0..7
            int off = (idx & 15) << 2;        // k offset 0..60
            const float* src;
            if (layer == 0)
                src = (t == 0) ? (h0l + (size_t)(bbase + row) * HID)
                               : (g_Y0 + ((size_t)t * BB + bbase + row) * HID);
            else
                src = (t == 0) ? (h0l + (size_t)(bbase + row) * HID)
                               : (out + ((size_t)(bbase + row) * TT + (t - 1)) * HID);
            float4 v = __ldcv((const float4*)(src + kbase + off));
            *(float4*)(h_s + row * 516 + kbase + off) = v;
        }
        __syncwarp();

        // ---- mainloop: 4x4 tile, k-pairs, 8 LDS.128 + 32 FFMA2 per 4k ----
        ull acc[4][4];
#pragma unroll
        for (int i = 0; i < 4; i++)
#pragma unroll
            for (int j = 0; j < 4; j++) acc[i][j] = 0ULL;

#pragma unroll 4
        for (int kk = 0; kk < 64; kk += 4) {
            int k = kbase + kk;
            ulonglong2 hv0 = *(const ulonglong2*)(h_s + (4 * bg + 0) * 516 + k);
            ulonglong2 hv1 = *(const ulonglong2*)(h_s + (4 * bg + 1) * 516 + k);
            ulonglong2 hv2 = *(const ulonglong2*)(h_s + (4 * bg + 2) * 516 + k);
            ulonglong2 hv3 = *(const ulonglong2*)(h_s + (4 * bg + 3) * 516 + k);
#pragma unroll
            for (int i = 0; i < 4; i++) {
                ulonglong2 wv = *(const ulonglong2*)(ws + (rg + 16 * i) * 516 + k);
                acc[i][0] = fma2(hv0.x, wv.x, acc[i][0]);
                acc[i][0] = fma2(hv0.y, wv.y, acc[i][0]);
                acc[i][1] = fma2(hv1.x, wv.x, acc[i][1]);
                acc[i][1] = fma2(hv1.y, wv.y, acc[i][1]);
                acc[i][2] = fma2(hv2.x, wv.x, acc[i][2]);
                acc[i][2] = fma2(hv2.y, wv.y, acc[i][2]);
                acc[i][3] = fma2(hv3.x, wv.x, acc[i][3]);
                acc[i][3] = fma2(hv3.y, wv.y, acc[i][3]);
            }
        }

        // ---- scatter k-split partials: red[(lane+32(i+4j))*9 + widx] ----
#pragma unroll
        for (int i = 0; i < 4; i++)
#pragma unroll
            for (int j = 0; j < 4; j++) {
                float lo, hi;
                unpack2(acc[i][j], lo, hi);
                red[(lane + 32 * (i + 4 * j)) * 9 + widx] = lo + hi;
            }
        __syncthreads();

        // ---- reduce 8 partials per cell (+G), 2 cells/thread -> gates_s ----
        {
            const float* rp0 = red + tid * 9;
            const float* rp1 = red + (tid + 256) * 9;
            float s0 = Gv0, s1 = Gv1;
#pragma unroll
            for (int p = 0; p < 8; p++) s0 += rp0[p];
#pragma unroll
            for (int p = 0; p < 8; p++) s1 += rp1[p];
            gates_s[rc0 * 8 + bc0] = s0;
            gates_s[rc1 * 8 + bc1] = s1;
        }
        __syncthreads();

        // ---- activations (tid<128): u=tid>>3, b=tid&7 ----
        if (tid < 128) {
            float xi = gates_s[tid];
            float xf = gates_s[128 + tid];
            float xg = gates_s[256 + tid];
            float xo = gates_s[384 + tid];
            float iv = 1.f / (1.f + __expf(-xi));
            float fv = 1.f / (1.f + __expf(-xf));
            float gv = 1.f - 2.f / (__expf(2.f * xg) + 1.f);
            float ov = 1.f / (1.f + __expf(-xo));
            float c = fv * creg + iv * gv;
            creg = c;
            float h = ov * (1.f - 2.f / (__expf(2.f * c) + 1.f));
            hseg[ab * 20 + au] = h;
            if (t == TT - 1) {
                outh[(size_t)(layer * BB + bbase + ab) * HID + j0 + au] = h;
                outc[(size_t)(layer * BB + bbase + ab) * HID + j0 + au] = creg;
            }
        }
        __syncthreads();

        // ---- publish 2KB + release flag ----
        if (tid < 32) {
            int b = tid >> 2, q = tid & 3;
            float4 hv = *(const float4*)(hseg + b * 20 + 4 * q);
            float* dst = (layer == 0)
                ? (g_Y0 + ((size_t)(t + 1) * BB + bbase + b) * HID + j0 + 4 * q)
                : (out + ((size_t)(bbase + b) * TT + t) * HID + j0 + 4 * q);
            __stcg((float4*)dst, hv);
            __syncwarp();
            if (tid == 0) {
                __threadfence();
                asm volatile("st.relaxed.gpu.global.u32 [%0], %1;"
                             :: "l"(myflag), "r"((unsigned)(t + 1)) : "memory");
            }
        }
        __syncthreads();
    }
}

// -------------------- launch --------------------
extern "C" void kernel_launch(void* const* d_in, const int* in_sizes, int n_in,
                              void* d_out, int out_size) {
    const float* input = (const float*)d_in[0];
    const float* h0    = (const float*)d_in[1];
    const float* c0    = (const float*)d_in[2];
    const float* W_ih  = (const float*)d_in[3];
    const float* W_hh  = (const float*)d_in[4];
    const float* b_ih  = (const float*)d_in[5];
    const float* b_hh  = (const float*)d_in[6];
    float* out = (float*)d_out;

    cudaFuncSetAttribute(recur_kernel, cudaFuncAttributeMaxDynamicSharedMemorySize, SM_TOTAL);

    float* Gptr;
    cudaGetSymbolAddress((void**)&Gptr, g_G);
    float* Y0ptr;
    cudaGetSymbolAddress((void**)&Y0ptr, g_Y0);

    dim3 ggrid(32, 256);

    // Layer 0 (gemm<0> zeroes layer-0 flags, stream-ordered before recur)
    gemm_kernel<0><<<ggrid, 256>>>(input, W_ih, b_ih, b_hh, Gptr);
    recur_kernel<<<NCTA, 256, SM_TOTAL>>>(0, W_hh, h0, c0, out);

    // Layer 1 (gemm<1> zeroes layer-1 flags; input = layer-0 outputs)
    gemm_kernel<1><<<ggrid, 256>>>(Y0ptr + BB * HID, W_ih + (size_t)G4 * HID,
                                   b_ih + G4, b_hh + G4, Gptr);
    recur_kernel<<<NCTA, 256, SM_TOTAL>>>(1, W_hh + (size_t)G4 * HID,
                                          h0 + BB * HID, c0 + BB * HID, out);
}

// round 15
// speedup vs baseline: 3.0628x; 1.0614x over previous
#include <cuda_runtime.h>
#include <cstdint>

#define BB   32
#define TT   1024
#define HID  512
#define G4   2048            // 4*HID
#define MROWS (BB*TT)        // 32768
#define NCTA 128
#define OUT_MAIN (BB*TT*HID) // 16777216

typedef unsigned long long ull;

__device__ __forceinline__ ull pack2(float x) {
    ull d; asm("mov.b64 %0, {%1, %1};" : "=l"(d) : "f"(x)); return d;
}
__device__ __forceinline__ ull fma2(ull a, ull b, ull c) {
    ull d; asm("fma.rn.f32x2 %0, %1, %2, %3;" : "=l"(d) : "l"(a), "l"(b), "l"(c)); return d;
}
__device__ __forceinline__ void unpack2(ull v, float& lo, float& hi) {
    asm("mov.b64 {%0, %1}, %2;" : "=f"(lo), "=f"(hi) : "l"(v));
}

// -------------------- device scratch --------------------
__device__ float g_G[(size_t)MROWS * G4];           // precomputed input-side gates
__device__ float g_Y0[(size_t)(TT + 1) * BB * HID]; // layer-0 h outputs (slot t+1 = h_t)
__device__ unsigned g_gf[2][NCTA * 32];             // per-CTA epoch flags, 128B padded

// -------------------- big GEMM (FFMA2); block(0,0) zeroes this layer's flags ----
template <int MODE>
__global__ __launch_bounds__(256) void gemm_kernel(
    const float* __restrict__ A,
    const float* __restrict__ W,
    const float* __restrict__ bih,
    const float* __restrict__ bhh,
    float* __restrict__ Gout)
{
    __shared__ float As[16 * 132];
    __shared__ float Bs[16 * 66];

    const int tid = threadIdx.x;
    const int bm = blockIdx.y;
    const int bn = blockIdx.x;
    const int ty = tid >> 4;
    const int tx = tid & 15;

    if (bm == 0 && bn == 0) {
        unsigned* ff = &g_gf[MODE][0];
#pragma unroll
        for (int i = 0; i < 16; i++) ff[tid + i * 256] = 0u;
    }

    ull acc2[8][2];
#pragma unroll
    for (int i = 0; i < 8; i++) { acc2[i][0] = 0ULL; acc2[i][1] = 0ULL; }

    for (int kt = 0; kt < HID; kt += 16) {
#pragma unroll
        for (int q = 0; q < 2; q++) {
            int idx = tid + q * 256;
            int lrow = idx >> 2;
            int lk = (idx & 3) << 2;
            int r = bm * 128 + lrow;
            const float* ap;
            if (MODE == 0)
                ap = A + ((size_t)(r & 31) * TT + (size_t)(r >> 5)) * HID;
            else
                ap = A + (size_t)r * HID;
            float4 v = *(const float4*)(ap + kt + lk);
            As[(lk + 0) * 132 + lrow] = v.x;
            As[(lk + 1) * 132 + lrow] = v.y;
            As[(lk + 2) * 132 + lrow] = v.z;
            As[(lk + 3) * 132 + lrow] = v.w;
        }
        {
            int ln = tid >> 2;
            int lk = (tid & 3) << 2;
            float4 v = *(const float4*)(W + (size_t)(bn * 64 + ln) * HID + kt + lk);
            Bs[(lk + 0) * 66 + ln] = v.x;
            Bs[(lk + 1) * 66 + ln] = v.y;
            Bs[(lk + 2) * 66 + ln] = v.z;
            Bs[(lk + 3) * 66 + ln] = v.w;
        }
        __syncthreads();

#pragma unroll
        for (int k = 0; k < 16; k++) {
            float4 a0 = *(const float4*)&As[k * 132 + 4 * ty];
            float4 a1 = *(const float4*)&As[k * 132 + 64 + 4 * ty];
            ull bp0 = *(const ull*)&Bs[k * 66 + 2 * tx];
            ull bp1 = *(const ull*)&Bs[k * 66 + 32 + 2 * tx];
            float av[8] = {a0.x, a0.y, a0.z, a0.w, a1.x, a1.y, a1.z, a1.w};
#pragma unroll
            for (int i = 0; i < 8; i++) {
                ull ad = pack2(av[i]);
                acc2[i][0] = fma2(ad, bp0, acc2[i][0]);
                acc2[i][1] = fma2(ad, bp1, acc2[i][1]);
            }
        }
        __syncthreads();
    }

    int c0 = bn * 64 + 2 * tx;
    int c1 = c0 + 32;
    float bias00 = bih[c0] + bhh[c0];
    float bias01 = bih[c0 + 1] + bhh[c0 + 1];
    float bias10 = bih[c1] + bhh[c1];
    float bias11 = bih[c1 + 1] + bhh[c1 + 1];
#pragma unroll
    for (int i = 0; i < 8; i++) {
        int m = (i < 4) ? (4 * ty + i) : (64 + 4 * ty + i - 4);
        size_t r = (size_t)(bm * 128 + m);
        float x, y;
        unpack2(acc2[i][0], x, y);
        *(float2*)(Gout + r * G4 + c0) = make_float2(x + bias00, y + bias01);
        unpack2(acc2[i][1], x, y);
        *(float2*)(Gout + r * G4 + c1) = make_float2(x + bias10, y + bias11);
    }
}

// -------------------- persistent recurrence: 512 threads, 16 k-sliced warps ------
// Group g = CTAs 32g..32g+31, batches 8g..8g+7. CTA cl: units j0=16cl (64 rows).
// Warp w (of 16): k-slice [32w,32w+32) -> needs only producers 2w, 2w+1.
// Lane (rg=lane&15, bgc=lane>>4): 4x4 tile rows {rg+16i} x batches {4bgc+j}.
// Scatter: red[cell*17 + w], cell = lane + 32*(i+4j).  One syncthreads per step.
// Act thread a(<128): u=a&15, bg=(a>>4)&1, j=a>>5, b=4bg+j; reduces its 4 gate
// cells (cbase + 32i) directly, does activation, writes hseg; bar.sync 1,128;
// warp0 publishes + flags.  Warps 4..15 run ahead (flag-gated, race-free).
//
// Smem (bytes):
//   ws   : float[64][516]  @ 0       (132096)
//   h_s  : float[8][516]   @ 132096  (16512)
//   red  : float[512*17]   @ 148608  (34816)
//   hseg : float[160]      @ 183424  (640)
#define SM_WS    0
#define SM_HS    132096
#define SM_RED   148608
#define SM_HSEG  183424
#define SM_TOTAL 184064

__global__ __launch_bounds__(512, 1) void recur_kernel(
    int layer,
    const float* __restrict__ Whh,
    const float* __restrict__ h0l,
    const float* __restrict__ c0l,
    float* __restrict__ out)
{
    extern __shared__ char smraw[];
    float* ws   = (float*)(smraw + SM_WS);
    float* h_s  = (float*)(smraw + SM_HS);
    float* red  = (float*)(smraw + SM_RED);
    float* hseg = (float*)(smraw + SM_HSEG);

    const int tid = threadIdx.x;
    const int cta = blockIdx.x;
    const int grp = cta >> 5;
    const int cl  = cta & 31;
    const int j0  = cl * 16;
    const int bbase = grp * 8;

    // ---- load Whh slice: 64 rows, eighth-row per thread ----
    {
        int r = tid >> 3, part = tid & 7;
        const float* src = Whh + ((size_t)((r >> 4) * HID + j0 + (r & 15))) * HID + part * 64;
        float* dst = ws + r * 516 + part * 64;
#pragma unroll
        for (int i = 0; i < 16; i++)
            *(float4*)(dst + i * 4) = *(const float4*)(src + i * 4);
    }

    // ---- act threads (tid<128): u=tid&15, bg=(tid>>4)&1, j=tid>>5, b=4bg+j ----
    const bool act = (tid < 128);
    const int au = tid & 15;
    const int abg = (tid >> 4) & 1;
    const int aj = tid >> 5;                   // valid for act threads only
    const int ab = 4 * abg + aj;
    const int cbase = au + 16 * abg + 128 * aj;   // + 32*i for gate type i
    float creg = 0.f;
    if (act) creg = c0l[(size_t)(bbase + ab) * HID + j0 + au];
    __syncthreads();

    const int widx = tid >> 5;
    const int lane = tid & 31;
    const int rg = lane & 15;
    const int bgc = lane >> 4;
    const int kbase = widx * 32;

    unsigned* myflag = &g_gf[layer][cta * 32];
    const unsigned* pollf = &g_gf[layer][(grp * 32 + 2 * widx + lane) * 32]; // lane<2

    const float* wp = ws + rg * 516 + kbase;       // rows rg+16i at +i*8256
    const float* hp = h_s + 4 * bgc * 516 + kbase; // batches 4bgc+j at +j*516

    float* outh = out + OUT_MAIN;
    float* outc = out + OUT_MAIN + 2 * BB * HID;

    for (int t = 0; t < TT; t++) {
        // ---- act threads prefetch their 4 input-side gate values ----
        float Gv[4];
        if (act) {
            const float* gro = g_G + ((size_t)t * BB + bbase + ab) * G4 + j0 + au;
#pragma unroll
            for (int ty2 = 0; ty2 < 4; ty2++) Gv[ty2] = gro[ty2 * HID];
        }

        // ---- per-warp wait: only 2 producers (lanes 0..1 poll) ----
        if (t > 0) {
            int sp = 0;
            while (true) {
                bool ok = true;
                if (lane < 2) {
                    unsigned v;
                    asm volatile("ld.acquire.gpu.global.u32 %0, [%1];"
                                 : "=r"(v) : "l"(pollf) : "memory");
                    ok = (v >= (unsigned)t);
                }
                if (__all_sync(0xffffffffu, ok)) break;
                if (++sp > 512) __nanosleep(20);
            }
        }

        // ---- per-warp stage: 8 batches x 32 k, 2 ldcv per lane ----
#pragma unroll
        for (int q = 0; q < 2; q++) {
            int idx = lane + 32 * q;          // 0..63
            int row = idx >> 3;               // 0..7
            int off = (idx & 7) << 2;         // 0..28
            const float* src;
            if (layer == 0)
                src = (t == 0) ? (h0l + (size_t)(bbase + row) * HID)
                               : (g_Y0 + ((size_t)t * BB + bbase + row) * HID);
            else
                src = (t == 0) ? (h0l + (size_t)(bbase + row) * HID)
                               : (out + ((size_t)(bbase + row) * TT + (t - 1)) * HID);
            float4 v = __ldcv((const float4*)(src + kbase + off));
            *(float4*)(h_s + row * 516 + kbase + off) = v;
        }
        __syncwarp();

        // ---- mainloop: 4x4 tile over 32 k (8 iters) ----
        ull acc[4][4];
#pragma unroll
        for (int i = 0; i < 4; i++)
#pragma unroll
            for (int j = 0; j < 4; j++) acc[i][j] = 0ULL;

#pragma unroll
        for (int kk = 0; kk < 32; kk += 4) {
            ulonglong2 hv0 = *(const ulonglong2*)(hp + 0 * 516 + kk);
            ulonglong2 hv1 = *(const ulonglong2*)(hp + 1 * 516 + kk);
            ulonglong2 hv2 = *(const ulonglong2*)(hp + 2 * 516 + kk);
            ulonglong2 hv3 = *(const ulonglong2*)(hp + 3 * 516 + kk);
#pragma unroll
            for (int i = 0; i < 4; i++) {
                ulonglong2 wv = *(const ulonglong2*)(wp + i * 8256 + kk);
                acc[i][0] = fma2(hv0.x, wv.x, acc[i][0]);
                acc[i][0] = fma2(hv0.y, wv.y, acc[i][0]);
                acc[i][1] = fma2(hv1.x, wv.x, acc[i][1]);
                acc[i][1] = fma2(hv1.y, wv.y, acc[i][1]);
                acc[i][2] = fma2(hv2.x, wv.x, acc[i][2]);
                acc[i][2] = fma2(hv2.y, wv.y, acc[i][2]);
                acc[i][3] = fma2(hv3.x, wv.x, acc[i][3]);
                acc[i][3] = fma2(hv3.y, wv.y, acc[i][3]);
            }
        }

        // ---- scatter k-split partials: red[(lane+32(i+4j))*17 + widx] ----
#pragma unroll
        for (int i = 0; i < 4; i++)
#pragma unroll
            for (int j = 0; j < 4; j++) {
                float lo, hi;
                unpack2(acc[i][j], lo, hi);
                red[(lane + 32 * (i + 4 * j)) * 17 + widx] = lo + hi;
            }
        __syncthreads();   // the ONLY block-wide sync per step

        // ---- act threads: fused reduce + activation + hseg; then publish ----
        if (act) {
            float x[4];
#pragma unroll
            for (int i = 0; i < 4; i++) {
                const float* rp = red + (cbase + 32 * i) * 17;
                float s0 = rp[0] + rp[1], s1 = rp[2] + rp[3];
                float s2 = rp[4] + rp[5], s3 = rp[6] + rp[7];
                float s4 = rp[8] + rp[9], s5 = rp[10] + rp[11];
                float s6 = rp[12] + rp[13], s7 = rp[14] + rp[15];
                x[i] = Gv[i] + (((s0 + s1) + (s2 + s3)) + ((s4 + s5) + (s6 + s7)));
            }
            float iv = 1.f / (1.f + __expf(-x[0]));
            float fv = 1.f / (1.f + __expf(-x[1]));
            float gv = 1.f - 2.f / (__expf(2.f * x[2]) + 1.f);
            float ov = 1.f / (1.f + __expf(-x[3]));
            float c = fv * creg + iv * gv;
            creg = c;
            float h = ov * (1.f - 2.f / (__expf(2.f * c) + 1.f));
            hseg[ab * 20 + au] = h;
            if (t == TT - 1) {
                outh[(size_t)(layer * BB + bbase + ab) * HID + j0 + au] = h;
                outc[(size_t)(layer * BB + bbase + ab) * HID + j0 + au] = creg;
            }
            asm volatile("bar.sync 1, 128;" ::: "memory");   // warps 0..3 only

            if (tid < 32) {
                int b = tid >> 2, q = tid & 3;
                float4 hv = *(const float4*)(hseg + b * 20 + 4 * q);
                float* dst = (layer == 0)
                    ? (g_Y0 + ((size_t)(t + 1) * BB + bbase + b) * HID + j0 + 4 * q)
                    : (out + ((size_t)(bbase + b) * TT + t) * HID + j0 + 4 * q);
                __stcg((float4*)dst, hv);
                __syncwarp();
                if (tid == 0) {
                    __threadfence();
                    asm volatile("st.relaxed.gpu.global.u32 [%0], %1;"
                                 :: "l"(myflag), "r"((unsigned)(t + 1)) : "memory");
                }
            }
        }
        // warps 4..15 run ahead; red overwrite is flag-gated -> race-free
    }
}

// -------------------- launch --------------------
extern "C" void kernel_launch(void* const* d_in, const int* in_sizes, int n_in,
                              void* d_out, int out_size) {
    const float* input = (const float*)d_in[0];
    const float* h0    = (const float*)d_in[1];
    const float* c0    = (const float*)d_in[2];
    const float* W_ih  = (const float*)d_in[3];
    const float* W_hh  = (const float*)d_in[4];
    const float* b_ih  = (const float*)d_in[5];
    const float* b_hh  = (const float*)d_in[6];
    float* out = (float*)d_out;

    cudaFuncSetAttribute(recur_kernel, cudaFuncAttributeMaxDynamicSharedMemorySize, SM_TOTAL);

    float* Gptr;
    cudaGetSymbolAddress((void**)&Gptr, g_G);
    float* Y0ptr;
    cudaGetSymbolAddress((void**)&Y0ptr, g_Y0);

    dim3 ggrid(32, 256);

    // Layer 0 (gemm<0> zeroes layer-0 flags, stream-ordered before recur)
    gemm_kernel<0><<<ggrid, 256>>>(input, W_ih, b_ih, b_hh, Gptr);
    recur_kernel<<<NCTA, 512, SM_TOTAL>>>(0, W_hh, h0, c0, out);

    // Layer 1 (gemm<1> zeroes layer-1 flags; input = layer-0 outputs)
    gemm_kernel<1><<<ggrid, 256>>>(Y0ptr + BB * HID, W_ih + (size_t)G4 * HID,
                                   b_ih + G4, b_hh + G4, Gptr);
    recur_kernel<<<NCTA, 512, SM_TOTAL>>>(1, W_hh + (size_t)G4 * HID,
                                          h0 + BB * HID, c0 + BB * HID, out);
}